// round 1
// baseline (speedup 1.0000x reference)
#include <cuda_runtime.h>
#include <math.h>

#define NODES   661
#define NGRAPH  128
#define NTOT    (NODES * NGRAPH)      // 84608
#define FDIM    64
#define EPG     (NODES * 8)           // 5288 edges per graph per edge set

// ---------------- device scratch (static allocation, allowed) ----------------
__device__ float g_eG[NTOT * FDIM];
__device__ float g_fG[NTOT * FDIM];
__device__ float g_eB[NTOT * FDIM];
__device__ float g_fB[NTOT * FDIM];
__device__ float g_e1[NTOT * FDIM];
__device__ float g_f1[NTOT * FDIM];
__device__ float g_e2[NTOT * FDIM];
__device__ float g_f2[NTOT * FDIM];
__device__ float g_e3[NTOT * FDIM];
__device__ float g_f3[NTOT * FDIM];
__device__ float g_ne[NTOT * FDIM];
__device__ float g_nf[NTOT * FDIM];
__device__ float g_att[8 * NGRAPH];   // [k in 0..7][graph]; 0..3 = e-side, 4..7 = f-side

// ---------------------------------------------------------------------------
__global__ void zero_att_kernel() {
    int i = threadIdx.x;
    if (i < 8 * NGRAPH) g_att[i] = 0.0f;
}

// ---------------------------------------------------------------------------
// SpMM: one CTA per (graph, feature-half). Accumulates in shared memory
// (no global atomics, no global zero-init). ES selects the output arrays.
// grid.x = 256 (128 graphs x 2 halves), 512 threads (16 warps).
template <int ES>
__global__ void spmm_kernel(const int* __restrict__ rows,
                            const int* __restrict__ cols,
                            const float* __restrict__ vals,
                            const float* __restrict__ e,
                            const float* __restrict__ f) {
    extern __shared__ float sm[];
    float* accE = sm;
    float* accF = sm + NODES * 32;

    const int g    = blockIdx.x >> 1;
    const int half = blockIdx.x & 1;
    const int tid  = threadIdx.x;

    for (int i = tid; i < NODES * 32; i += blockDim.x) {
        accE[i] = 0.0f;
        accF[i] = 0.0f;
    }
    __syncthreads();

    const int lane  = tid & 31;
    const int wid   = tid >> 5;            // 0..15
    const int off   = half * 32 + lane;    // feature offset
    const int gbase = g * NODES;

    int i   = g * EPG + wid;
    int end = (g + 1) * EPG;

    // 4-edge unroll for MLP
    for (; i + 48 < end; i += 64) {
        const int ia = i, ib = i + 16, ic = i + 32, id = i + 48;
        int r0 = rows[ia] - gbase, r1 = rows[ib] - gbase, r2 = rows[ic] - gbase, r3 = rows[id] - gbase;
        int c0 = cols[ia], c1 = cols[ib], c2 = cols[ic], c3 = cols[id];
        float v0 = vals[ia], v1 = vals[ib], v2 = vals[ic], v3 = vals[id];
        float e0 = e[c0 * FDIM + off], e1v = e[c1 * FDIM + off], e2v = e[c2 * FDIM + off], e3v = e[c3 * FDIM + off];
        float f0 = f[c0 * FDIM + off], f1v = f[c1 * FDIM + off], f2v = f[c2 * FDIM + off], f3v = f[c3 * FDIM + off];
        atomicAdd(&accE[r0 * 32 + lane], v0 * e0);
        atomicAdd(&accF[r0 * 32 + lane], v0 * f0);
        atomicAdd(&accE[r1 * 32 + lane], v1 * e1v);
        atomicAdd(&accF[r1 * 32 + lane], v1 * f1v);
        atomicAdd(&accE[r2 * 32 + lane], v2 * e2v);
        atomicAdd(&accF[r2 * 32 + lane], v2 * f2v);
        atomicAdd(&accE[r3 * 32 + lane], v3 * e3v);
        atomicAdd(&accF[r3 * 32 + lane], v3 * f3v);
    }
    for (; i < end; i += 16) {
        int r = rows[i] - gbase;
        int c = cols[i];
        float v = vals[i];
        float ev = e[c * FDIM + off];
        float fv = f[c * FDIM + off];
        atomicAdd(&accE[r * 32 + lane], v * ev);
        atomicAdd(&accF[r * 32 + lane], v * fv);
    }
    __syncthreads();

    float* outE;
    float* outF;
    if (ES == 0)      { outE = g_eG; outF = g_fG; }
    else if (ES == 1) { outE = g_eB; outF = g_fB; }
    else if (ES == 2) { outE = g_e1; outF = g_f1; }
    else              { outE = g_e2; outF = g_f2; }

    for (int k = tid; k < NODES * 32; k += blockDim.x) {
        int r = k >> 5, c = k & 31;
        int gi = (gbase + r) * FDIM + half * 32 + c;
        outE[gi] = accE[k];
        outF[gi] = accF[k];
    }
}

// ---------------------------------------------------------------------------
// Elementwise math + attention partial sums.
// grid = NTOT/4 blocks of 256 threads; each thread = one (row, feat).
__device__ __forceinline__ float warp_sum(float v) {
    #pragma unroll
    for (int o = 16; o > 0; o >>= 1) v += __shfl_xor_sync(0xffffffffu, v, o);
    return v;
}

__global__ void elem_kernel(const float* __restrict__ e, const float* __restrict__ f,
                            const float* __restrict__ Pd, const float* __restrict__ Qd,
                            const float* __restrict__ Gd, const float* __restrict__ Bd,
                            const float* __restrict__ w_ae, const float* __restrict__ w_af) {
    const int tid  = threadIdx.x;
    const int feat = tid & 63;
    const int row  = blockIdx.x * 4 + (tid >> 6);
    const int idx  = row * FDIM + feat;

    float ev = e[idx], fv = f[idx];
    float eG = g_eG[idx], fG = g_fG[idx], eB = g_eB[idx], fB = g_fB[idx];
    float e1v = g_e1[idx], f1v = g_f1[idx], e2v = g_e2[idx], f2v = g_f2[idx];
    float P = Pd[row], Q = Qd[row], G = Gd[row], B = Bd[row];

    float v2    = ev * ev + fv * fv;
    float invb  = 1.0f / (v2 + 0.1f);
    float alpha = (P * ev + Q * fv) * invb - eG - fB;
    float beta  = (Q * ev - P * fv) * invb + fG + eB;
    float invgb = 1.0f / (G * G + B * B);
    float e3 = (alpha * G + beta * B) * invgb;
    float f3 = (beta * G - alpha * B) * invgb;

    float b1 = eG - fB;
    float b2 = fG + eB;
    float P_ = P - v2 * G;
    float Q_ = Q + v2 * B;
    float ne = (P_ * b1 + Q_ * b2) * invgb;
    float nf = (P_ * b2 - Q_ * b1) * invgb;

    g_e3[idx] = e3;
    g_f3[idx] = f3;
    g_ne[idx] = ne;
    g_nf[idx] = nf;

    float wa = w_ae[feat];
    float wf = w_af[feat];
    float c0 = warp_sum(wa * e3);
    float c1 = warp_sum(wa * ne);
    float c2 = warp_sum(wa * e1v);
    float c3 = warp_sum(wa * e2v);
    float c4 = warp_sum(wf * f3);
    float c5 = warp_sum(wf * nf);
    float c6 = warp_sum(wf * f1v);
    float c7 = warp_sum(wf * f2v);

    int lane = tid & 31;
    float sel = 0.0f;
    if (lane == 0) sel = c0;
    else if (lane == 1) sel = c1;
    else if (lane == 2) sel = c2;
    else if (lane == 3) sel = c3;
    else if (lane == 4) sel = c4;
    else if (lane == 5) sel = c5;
    else if (lane == 6) sel = c6;
    else if (lane == 7) sel = c7;
    if (lane < 8) atomicAdd(&g_att[lane * NGRAPH + row / NODES], sel);
}

// ---------------------------------------------------------------------------
// Fused concat-GEMM + tanh, using packed fma.rn.f32x2.
// block: 256 threads = 256 rows; grid: (ceil(NTOT/256), 2 sides).
// Dynamic smem: Wsm[320*66] + xs[256*65].
__device__ __forceinline__ unsigned long long fma2(unsigned long long a,
                                                   unsigned long long b,
                                                   unsigned long long c) {
    unsigned long long d;
    asm("fma.rn.f32x2 %0, %1, %2, %3;" : "=l"(d) : "l"(a), "l"(b), "l"(c));
    return d;
}

__global__ void gemm_kernel(const float* __restrict__ e, const float* __restrict__ f,
                            const float* __restrict__ W1, const float* __restrict__ bv1,
                            const float* __restrict__ W2, const float* __restrict__ bv2,
                            const float* __restrict__ b_ae, const float* __restrict__ b_af,
                            float* __restrict__ out) {
    extern __shared__ float sm[];
    float* Wsm = sm;               // [320][66] k-major, padded
    float* xs  = sm + 320 * 66;    // [256][65]

    const int side    = blockIdx.y;
    const int tid     = threadIdx.x;
    const int rowbase = blockIdx.x * 256;
    const int nrows   = min(256, NTOT - rowbase);

    const float* W  = side ? W2 : W1;
    const float* bv = side ? bv2 : bv1;

    // W transpose load: Wsm[k*66+j] = W[j*320+k]
    for (int i = tid; i < 320 * 64; i += 256) {
        int j = i / 320;
        int k = i - j * 320;
        Wsm[k * 66 + j] = W[i];
    }

    const float* srcs[5];
    if (side == 0) { srcs[0] = g_e3; srcs[1] = g_ne; srcs[2] = g_e1; srcs[3] = g_e2; srcs[4] = e; }
    else           { srcs[0] = g_f3; srcs[1] = g_nf; srcs[2] = g_f1; srcs[3] = g_f2; srcs[4] = f; }

    // per-row attention scalars
    const int row = rowbase + tid;
    float a[5];
    a[4] = 1.0f;
    if (tid < nrows) {
        int gph = row / NODES;
        float bias = side ? b_af[0] : b_ae[0];
        float ssum = 1e-4f;
        #pragma unroll
        for (int k = 0; k < 4; k++) {
            float s  = g_att[(side * 4 + k) * NGRAPH + gph] * (1.0f / (float)NODES) + bias;
            float sg = 1.0f / (1.0f + expf(-s));
            a[k] = sg;
            ssum += sg;
        }
        float inv = 1.0f / ssum;
        #pragma unroll
        for (int k = 0; k < 4; k++) a[k] *= inv;
    } else {
        a[0] = a[1] = a[2] = a[3] = 0.0f;
    }

    // accumulators initialized with bias
    unsigned long long acc[32];
    #pragma unroll
    for (int j2 = 0; j2 < 32; j2++) {
        union { float2 f2; unsigned long long u; } ub;
        ub.f2 = make_float2(bv[2 * j2], bv[2 * j2 + 1]);
        acc[j2] = ub.u;
    }

    for (int s = 0; s < 5; s++) {
        __syncthreads();
        const float* src = srcs[s] + (size_t)rowbase * FDIM;
        for (int i = tid; i < nrows * FDIM; i += 256) {
            xs[(i >> 6) * 65 + (i & 63)] = src[i];
        }
        __syncthreads();
        if (tid < nrows) {
            const float as = a[s];
            const float* xr = &xs[tid * 65];
            #pragma unroll 4
            for (int k = 0; k < 64; k++) {
                float xv = xr[k] * as;
                union { float2 f2; unsigned long long u; } ux;
                ux.f2 = make_float2(xv, xv);
                const unsigned long long* wrow =
                    (const unsigned long long*)&Wsm[(s * 64 + k) * 66];
                #pragma unroll
                for (int j2 = 0; j2 < 32; j2++) {
                    acc[j2] = fma2(ux.u, wrow[j2], acc[j2]);
                }
            }
        }
    }

    if (tid < nrows) {
        float* op = out + (size_t)side * NTOT * FDIM + (size_t)row * FDIM;
        #pragma unroll
        for (int j4 = 0; j4 < 16; j4++) {
            union { float2 f2; unsigned long long u; } a0, a1;
            a0.u = acc[2 * j4];
            a1.u = acc[2 * j4 + 1];
            float4 v;
            v.x = tanhf(a0.f2.x);
            v.y = tanhf(a0.f2.y);
            v.z = tanhf(a1.f2.x);
            v.w = tanhf(a1.f2.y);
            ((float4*)op)[j4] = v;
        }
    }
}

// ---------------------------------------------------------------------------
extern "C" void kernel_launch(void* const* d_in, const int* in_sizes, int n_in,
                              void* d_out, int out_size) {
    const float* e     = (const float*)d_in[0];
    const float* f     = (const float*)d_in[1];
    const int*   rowsG = (const int*)d_in[2];
    const int*   colsG = (const int*)d_in[3];
    const float* valsG = (const float*)d_in[4];
    const int*   rowsB = (const int*)d_in[5];
    const int*   colsB = (const int*)d_in[6];
    const float* valsB = (const float*)d_in[7];
    const int*   rows1 = (const int*)d_in[8];
    const int*   cols1 = (const int*)d_in[9];
    const float* vals1 = (const float*)d_in[10];
    const int*   rows2 = (const int*)d_in[11];
    const int*   cols2 = (const int*)d_in[12];
    const float* vals2 = (const float*)d_in[13];
    const float* G_diag = (const float*)d_in[14];
    const float* B_diag = (const float*)d_in[15];
    const float* Pd    = (const float*)d_in[16];
    const float* Qd    = (const float*)d_in[17];
    const float* W_v1  = (const float*)d_in[18];
    const float* b_v1  = (const float*)d_in[19];
    const float* W_v2  = (const float*)d_in[20];
    const float* b_v2  = (const float*)d_in[21];
    const float* w_ae  = (const float*)d_in[22];
    const float* b_ae  = (const float*)d_in[23];
    const float* w_af  = (const float*)d_in[24];
    const float* b_af  = (const float*)d_in[25];
    float* out = (float*)d_out;

    const int spmm_smem = NODES * 32 * 2 * (int)sizeof(float);        // 169216
    const int gemm_smem = (320 * 66 + 256 * 65) * (int)sizeof(float); // 151040

    cudaFuncSetAttribute(spmm_kernel<0>, cudaFuncAttributeMaxDynamicSharedMemorySize, spmm_smem);
    cudaFuncSetAttribute(spmm_kernel<1>, cudaFuncAttributeMaxDynamicSharedMemorySize, spmm_smem);
    cudaFuncSetAttribute(spmm_kernel<2>, cudaFuncAttributeMaxDynamicSharedMemorySize, spmm_smem);
    cudaFuncSetAttribute(spmm_kernel<3>, cudaFuncAttributeMaxDynamicSharedMemorySize, spmm_smem);
    cudaFuncSetAttribute(gemm_kernel, cudaFuncAttributeMaxDynamicSharedMemorySize, gemm_smem);

    zero_att_kernel<<<1, 1024>>>();

    spmm_kernel<0><<<NGRAPH * 2, 512, spmm_smem>>>(rowsG, colsG, valsG, e, f);
    spmm_kernel<1><<<NGRAPH * 2, 512, spmm_smem>>>(rowsB, colsB, valsB, e, f);
    spmm_kernel<2><<<NGRAPH * 2, 512, spmm_smem>>>(rows1, cols1, vals1, e, f);
    spmm_kernel<3><<<NGRAPH * 2, 512, spmm_smem>>>(rows2, cols2, vals2, e, f);

    elem_kernel<<<NTOT / 4, 256>>>(e, f, Pd, Qd, G_diag, B_diag, w_ae, w_af);

    dim3 ggrid((NTOT + 255) / 256, 2);
    gemm_kernel<<<ggrid, 256, gemm_smem>>>(e, f, W_v1, b_v1, W_v2, b_v2, b_ae, b_af, out);
}

// round 2
// speedup vs baseline: 2.1149x; 2.1149x over previous
#include <cuda_runtime.h>
#include <math.h>

#define NODES   661
#define NGRAPH  128
#define NTOT    (NODES * NGRAPH)      // 84608
#define FDIM    64
#define EPG     (NODES * 8)           // 5288 edges per graph per edge set
#define NNZ     (NTOT * 8)            // 676864 per edge set

// ---------------- device scratch (static allocation, allowed) ----------------
__device__ int   g_cnt   [4 * NTOT];
__device__ int   g_start [4 * NTOT];
__device__ int   g_cursor[4 * NTOT];
__device__ int   g_scol  [4 * NNZ];
__device__ float g_sval  [4 * NNZ];

__device__ float g_e1[NTOT * FDIM];
__device__ float g_f1[NTOT * FDIM];
__device__ float g_e2[NTOT * FDIM];
__device__ float g_f2[NTOT * FDIM];
__device__ float g_e3[NTOT * FDIM];
__device__ float g_f3[NTOT * FDIM];
__device__ float g_ne[NTOT * FDIM];
__device__ float g_nf[NTOT * FDIM];
__device__ float g_att[8 * NGRAPH];   // [k 0..7][graph]; 0..3 e-side, 4..7 f-side

// ---------------------------------------------------------------------------
// K1: zero counters + attention accumulators
__global__ void zero_kernel() {
    int i = blockIdx.x * blockDim.x + threadIdx.x;
    int stride = gridDim.x * blockDim.x;
    for (int k = i; k < 4 * NTOT; k += stride) g_cnt[k] = 0;
    if (i < 8 * NGRAPH) g_att[i] = 0.0f;
}

// K2: per-row histogram over all 4 edge sets
__global__ void hist_kernel(const int* __restrict__ r0, const int* __restrict__ r1,
                            const int* __restrict__ r2, const int* __restrict__ r3) {
    int s = blockIdx.y;
    const int* rw = (s == 0) ? r0 : (s == 1) ? r1 : (s == 2) ? r2 : r3;
    int i = blockIdx.x * blockDim.x + threadIdx.x;
    if (i < NNZ) atomicAdd(&g_cnt[s * NTOT + rw[i]], 1);
}

// K3: per (set, graph) exclusive scan -> row start positions (flat across sets)
__global__ void scan_kernel() {
    __shared__ int sm[1024];
    int s = blockIdx.x >> 7;
    int g = blockIdx.x & 127;
    int t = threadIdx.x;
    int base = s * NTOT + g * NODES;
    int v = (t < NODES) ? g_cnt[base + t] : 0;
    sm[t] = v;
    __syncthreads();
    #pragma unroll
    for (int off = 1; off < 1024; off <<= 1) {
        int add = (t >= off) ? sm[t - off] : 0;
        __syncthreads();
        sm[t] += add;
        __syncthreads();
    }
    if (t < NODES) {
        int start = s * NNZ + g * EPG + sm[t] - v;   // exclusive
        g_start[base + t]  = start;
        g_cursor[base + t] = start;
    }
}

// K4: scatter edges into row-sorted order
__global__ void scatter_kernel(const int* __restrict__ r0, const int* __restrict__ c0, const float* __restrict__ v0,
                               const int* __restrict__ r1, const int* __restrict__ c1, const float* __restrict__ v1,
                               const int* __restrict__ r2, const int* __restrict__ c2, const float* __restrict__ v2,
                               const int* __restrict__ r3, const int* __restrict__ c3, const float* __restrict__ v3) {
    int s = blockIdx.y;
    const int*   rw = (s == 0) ? r0 : (s == 1) ? r1 : (s == 2) ? r2 : r3;
    const int*   cw = (s == 0) ? c0 : (s == 1) ? c1 : (s == 2) ? c2 : c3;
    const float* vw = (s == 0) ? v0 : (s == 1) ? v1 : (s == 2) ? v2 : v3;
    int i = blockIdx.x * blockDim.x + threadIdx.x;
    if (i < NNZ) {
        int row = rw[i];
        int p = atomicAdd(&g_cursor[s * NTOT + row], 1);
        g_scol[p] = cw[i];
        g_sval[p] = vw[i];
    }
}

// ---------------------------------------------------------------------------
__device__ __forceinline__ float warp_sum(float v) {
    #pragma unroll
    for (int o = 16; o > 0; o >>= 1) v += __shfl_xor_sync(0xffffffffu, v, o);
    return v;
}

// K5: fused SpMM (4 sets, CSR, no atomics) + elementwise math + attention sums.
// One warp per row; lane covers features {2*lane, 2*lane+1} as float2.
__global__ void spmm_fused_kernel(const float* __restrict__ e, const float* __restrict__ f,
                                  const float* __restrict__ Pd, const float* __restrict__ Qd,
                                  const float* __restrict__ Gd, const float* __restrict__ Bd,
                                  const float* __restrict__ w_ae, const float* __restrict__ w_af) {
    int warp = (blockIdx.x * blockDim.x + threadIdx.x) >> 5;
    int lane = threadIdx.x & 31;
    if (warp >= NTOT) return;
    const int r = warp;

    const float2* e2p = (const float2*)e;
    const float2* f2p = (const float2*)f;

    float2 res[8];   // eG,fG,eB,fB,e1,f1,e2,f2

    #pragma unroll
    for (int s = 0; s < 4; s++) {
        float2 aE = make_float2(0.f, 0.f);
        float2 aF = make_float2(0.f, 0.f);
        int st  = g_start[s * NTOT + r];
        int len = g_cnt[s * NTOT + r];
        for (int base = 0; base < len; base += 32) {
            int rem = min(32, len - base);
            int c = 0; float v = 0.f;
            if (lane < rem) {
                c = g_scol[st + base + lane];
                v = g_sval[st + base + lane];
            }
            for (int j0 = 0; j0 < rem; j0 += 8) {
                float2 ge[8], gf[8]; float vv[8];
                #pragma unroll
                for (int j = 0; j < 8; j++) {
                    int k = j0 + j;
                    int   ck = __shfl_sync(0xffffffffu, c, k & 31);
                    float vk = __shfl_sync(0xffffffffu, v, k & 31);
                    if (k < rem) {
                        ge[j] = __ldg(&e2p[ck * 32 + lane]);
                        gf[j] = __ldg(&f2p[ck * 32 + lane]);
                        vv[j] = vk;
                    } else {
                        ge[j] = make_float2(0.f, 0.f);
                        gf[j] = make_float2(0.f, 0.f);
                        vv[j] = 0.f;
                    }
                }
                #pragma unroll
                for (int j = 0; j < 8; j++) {
                    aE.x += vv[j] * ge[j].x;  aE.y += vv[j] * ge[j].y;
                    aF.x += vv[j] * gf[j].x;  aF.y += vv[j] * gf[j].y;
                }
            }
        }
        res[2 * s]     = aE;
        res[2 * s + 1] = aF;
    }

    float2 eG = res[0], fG = res[1], eB = res[2], fB = res[3];
    float2 e1v = res[4], f1v = res[5], e2v = res[6], f2v = res[7];

    float2 ev = e2p[r * 32 + lane];
    float2 fv = f2p[r * 32 + lane];
    float P = Pd[r], Q = Qd[r], G = Gd[r], B = Bd[r];
    float invgb = 1.0f / (G * G + B * B);

    float2 e3, f3, ne, nf;
    {
        // component x
        float v2   = ev.x * ev.x + fv.x * fv.x;
        float invb = 1.0f / (v2 + 0.1f);
        float alpha = (P * ev.x + Q * fv.x) * invb - eG.x - fB.x;
        float beta  = (Q * ev.x - P * fv.x) * invb + fG.x + eB.x;
        e3.x = (alpha * G + beta * B) * invgb;
        f3.x = (beta * G - alpha * B) * invgb;
        float b1 = eG.x - fB.x, b2 = fG.x + eB.x;
        float P_ = P - v2 * G, Q_ = Q + v2 * B;
        ne.x = (P_ * b1 + Q_ * b2) * invgb;
        nf.x = (P_ * b2 - Q_ * b1) * invgb;
        // component y
        v2   = ev.y * ev.y + fv.y * fv.y;
        invb = 1.0f / (v2 + 0.1f);
        alpha = (P * ev.y + Q * fv.y) * invb - eG.y - fB.y;
        beta  = (Q * ev.y - P * fv.y) * invb + fG.y + eB.y;
        e3.y = (alpha * G + beta * B) * invgb;
        f3.y = (beta * G - alpha * B) * invgb;
        b1 = eG.y - fB.y; b2 = fG.y + eB.y;
        P_ = P - v2 * G;  Q_ = Q + v2 * B;
        ne.y = (P_ * b1 + Q_ * b2) * invgb;
        nf.y = (P_ * b2 - Q_ * b1) * invgb;
    }

    ((float2*)g_e3)[r * 32 + lane] = e3;
    ((float2*)g_f3)[r * 32 + lane] = f3;
    ((float2*)g_ne)[r * 32 + lane] = ne;
    ((float2*)g_nf)[r * 32 + lane] = nf;
    ((float2*)g_e1)[r * 32 + lane] = e1v;
    ((float2*)g_f1)[r * 32 + lane] = f1v;
    ((float2*)g_e2)[r * 32 + lane] = e2v;
    ((float2*)g_f2)[r * 32 + lane] = f2v;

    float2 wa = __ldg(&((const float2*)w_ae)[lane]);
    float2 wf = __ldg(&((const float2*)w_af)[lane]);

    float c0 = warp_sum(wa.x * e3.x  + wa.y * e3.y);
    float c1 = warp_sum(wa.x * ne.x  + wa.y * ne.y);
    float c2 = warp_sum(wa.x * e1v.x + wa.y * e1v.y);
    float c3 = warp_sum(wa.x * e2v.x + wa.y * e2v.y);
    float c4 = warp_sum(wf.x * f3.x  + wf.y * f3.y);
    float c5 = warp_sum(wf.x * nf.x  + wf.y * nf.y);
    float c6 = warp_sum(wf.x * f1v.x + wf.y * f1v.y);
    float c7 = warp_sum(wf.x * f2v.x + wf.y * f2v.y);

    float sel = 0.0f;
    if      (lane == 0) sel = c0;
    else if (lane == 1) sel = c1;
    else if (lane == 2) sel = c2;
    else if (lane == 3) sel = c3;
    else if (lane == 4) sel = c4;
    else if (lane == 5) sel = c5;
    else if (lane == 6) sel = c6;
    else if (lane == 7) sel = c7;
    if (lane < 8) atomicAdd(&g_att[lane * NGRAPH + r / NODES], sel);
}

// ---------------------------------------------------------------------------
// K6: register-blocked concat-GEMM + tanh. Thread tile 8 rows x 8 cols (f32x2).
// Block 256 threads -> 256 rows x 64 cols. smem ~88KB -> 2 CTAs/SM.
__device__ __forceinline__ unsigned long long fma2(unsigned long long a,
                                                   unsigned long long b,
                                                   unsigned long long c) {
    unsigned long long d;
    asm("fma.rn.f32x2 %0, %1, %2, %3;" : "=l"(d) : "l"(a), "l"(b), "l"(c));
    return d;
}
__device__ __forceinline__ unsigned long long pack2(float x) {
    unsigned long long d;
    asm("mov.b64 %0, {%1, %1};" : "=l"(d) : "f"(x));
    return d;
}
__device__ __forceinline__ float tanh_approx(float x) {
    float y;
    asm("tanh.approx.f32 %0, %1;" : "=f"(y) : "f"(x));
    return y;
}

#define XS_PITCH 65
#define W_PITCH  68

__global__ void __launch_bounds__(256, 2)
gemm_kernel(const float* __restrict__ e, const float* __restrict__ f,
            const float* __restrict__ W1, const float* __restrict__ bv1,
            const float* __restrict__ W2, const float* __restrict__ bv2,
            const float* __restrict__ b_ae, const float* __restrict__ b_af,
            float* __restrict__ out) {
    extern __shared__ float sm[];
    float* xs   = sm;                         // [256][65]
    float* Wsm  = sm + 256 * XS_PITCH;        // [64][68]
    float* as_s = Wsm + 64 * W_PITCH;         // [4][256]

    const int side    = blockIdx.y;
    const int tid     = threadIdx.x;
    const int rowbase = blockIdx.x * 256;
    const int nrows   = min(256, NTOT - rowbase);

    const float* W  = side ? W2 : W1;
    const float* bv = side ? bv2 : bv1;

    // attention coefficients per row
    if (tid < nrows) {
        int gph = (rowbase + tid) / NODES;
        float bias = side ? b_af[0] : b_ae[0];
        float ssum = 1e-4f;
        float av[4];
        #pragma unroll
        for (int k = 0; k < 4; k++) {
            float sc = g_att[(side * 4 + k) * NGRAPH + gph] * (1.0f / (float)NODES) + bias;
            float sg = 1.0f / (1.0f + expf(-sc));
            av[k] = sg;
            ssum += sg;
        }
        float inv = 1.0f / ssum;
        #pragma unroll
        for (int k = 0; k < 4; k++) as_s[k * 256 + tid] = av[k] * inv;
    } else {
        #pragma unroll
        for (int k = 0; k < 4; k++) as_s[k * 256 + tid] = 0.0f;
    }

    const int cg = tid & 7;    // col group: cols cg*8 .. cg*8+7
    const int rg = tid >> 3;   // row group: rows rg*8 .. rg*8+7

    unsigned long long acc[8][4];
    {
        #pragma unroll
        for (int j2 = 0; j2 < 4; j2++) {
            float b0 = bv[cg * 8 + 2 * j2];
            float b1 = bv[cg * 8 + 2 * j2 + 1];
            unsigned long long bb;
            asm("mov.b64 %0, {%1, %2};" : "=l"(bb) : "f"(b0), "f"(b1));
            #pragma unroll
            for (int i = 0; i < 8; i++) acc[i][j2] = bb;
        }
    }

    const float* srcs[5];
    if (side == 0) { srcs[0] = g_e3; srcs[1] = g_ne; srcs[2] = g_e1; srcs[3] = g_e2; srcs[4] = e; }
    else           { srcs[0] = g_f3; srcs[1] = g_nf; srcs[2] = g_f1; srcs[3] = g_f2; srcs[4] = f; }

    for (int s = 0; s < 5; s++) {
        __syncthreads();
        // stage x, pre-scaled by attention coefficient
        const float* src = srcs[s] + (size_t)rowbase * FDIM;
        for (int i = tid; i < nrows * FDIM; i += 256) {
            int rr = i >> 6, kk = i & 63;
            float a = (s < 4) ? as_s[s * 256 + rr] : 1.0f;
            xs[rr * XS_PITCH + kk] = src[i] * a;
        }
        // stage W chunk transposed: Wsm[k][j] = W[j][s*64+k]
        for (int i = tid; i < 4096; i += 256) {
            int j = i >> 6, k = i & 63;
            Wsm[k * W_PITCH + j] = W[j * 320 + s * 64 + k];
        }
        __syncthreads();

        for (int k = 0; k < 64; k++) {
            ulonglong2 wA = *reinterpret_cast<const ulonglong2*>(&Wsm[k * W_PITCH + cg * 8]);
            ulonglong2 wB = *reinterpret_cast<const ulonglong2*>(&Wsm[k * W_PITCH + cg * 8 + 4]);
            unsigned long long w2[4] = { wA.x, wA.y, wB.x, wB.y };
            unsigned long long xp[8];
            #pragma unroll
            for (int i = 0; i < 8; i++) xp[i] = pack2(xs[(rg * 8 + i) * XS_PITCH + k]);
            #pragma unroll
            for (int i = 0; i < 8; i++) {
                #pragma unroll
                for (int j2 = 0; j2 < 4; j2++)
                    acc[i][j2] = fma2(xp[i], w2[j2], acc[i][j2]);
            }
        }
    }

    // epilogue: tanh + store
    #pragma unroll
    for (int i = 0; i < 8; i++) {
        int lr = rg * 8 + i;
        if (lr < nrows) {
            int row = rowbase + lr;
            float* op = out + (size_t)side * NTOT * FDIM + (size_t)row * FDIM + cg * 8;
            union { unsigned long long u; float2 f2; } u0, u1, u2, u3;
            u0.u = acc[i][0]; u1.u = acc[i][1]; u2.u = acc[i][2]; u3.u = acc[i][3];
            float4 o0, o1;
            o0.x = tanh_approx(u0.f2.x); o0.y = tanh_approx(u0.f2.y);
            o0.z = tanh_approx(u1.f2.x); o0.w = tanh_approx(u1.f2.y);
            o1.x = tanh_approx(u2.f2.x); o1.y = tanh_approx(u2.f2.y);
            o1.z = tanh_approx(u3.f2.x); o1.w = tanh_approx(u3.f2.y);
            ((float4*)op)[0] = o0;
            ((float4*)op)[1] = o1;
        }
    }
}

// ---------------------------------------------------------------------------
extern "C" void kernel_launch(void* const* d_in, const int* in_sizes, int n_in,
                              void* d_out, int out_size) {
    const float* e     = (const float*)d_in[0];
    const float* f     = (const float*)d_in[1];
    const int*   rowsG = (const int*)d_in[2];
    const int*   colsG = (const int*)d_in[3];
    const float* valsG = (const float*)d_in[4];
    const int*   rowsB = (const int*)d_in[5];
    const int*   colsB = (const int*)d_in[6];
    const float* valsB = (const float*)d_in[7];
    const int*   rows1 = (const int*)d_in[8];
    const int*   cols1 = (const int*)d_in[9];
    const float* vals1 = (const float*)d_in[10];
    const int*   rows2 = (const int*)d_in[11];
    const int*   cols2 = (const int*)d_in[12];
    const float* vals2 = (const float*)d_in[13];
    const float* G_diag = (const float*)d_in[14];
    const float* B_diag = (const float*)d_in[15];
    const float* Pd    = (const float*)d_in[16];
    const float* Qd    = (const float*)d_in[17];
    const float* W_v1  = (const float*)d_in[18];
    const float* b_v1  = (const float*)d_in[19];
    const float* W_v2  = (const float*)d_in[20];
    const float* b_v2  = (const float*)d_in[21];
    const float* w_ae  = (const float*)d_in[22];
    const float* b_ae  = (const float*)d_in[23];
    const float* w_af  = (const float*)d_in[24];
    const float* b_af  = (const float*)d_in[25];
    float* out = (float*)d_out;

    const int gemm_smem = (256 * XS_PITCH + 64 * W_PITCH + 4 * 256) * (int)sizeof(float);
    static int configured = -1;
    if (configured < 0) {
        cudaFuncSetAttribute(gemm_kernel, cudaFuncAttributeMaxDynamicSharedMemorySize, gemm_smem);
        configured = 1;
    }

    zero_kernel<<<512, 256>>>();

    dim3 egrid((NNZ + 1023) / 1024, 4);
    hist_kernel<<<egrid, 1024>>>(rowsG, rowsB, rows1, rows2);

    scan_kernel<<<512, 1024>>>();

    scatter_kernel<<<egrid, 1024>>>(rowsG, colsG, valsG,
                                    rowsB, colsB, valsB,
                                    rows1, cols1, vals1,
                                    rows2, cols2, vals2);

    spmm_fused_kernel<<<(NTOT + 7) / 8, 256>>>(e, f, Pd, Qd, G_diag, B_diag, w_ae, w_af);

    dim3 ggrid((NTOT + 255) / 256, 2);
    gemm_kernel<<<ggrid, 256, gemm_smem>>>(e, f, W_v1, b_v1, W_v2, b_v2, b_ae, b_af, out);
}

// round 3
// speedup vs baseline: 2.2215x; 1.0504x over previous
#include <cuda_runtime.h>
#include <math.h>

#define NODES   661
#define NGRAPH  128
#define NTOT    (NODES * NGRAPH)      // 84608
#define FDIM    64
#define EPG     (NODES * 8)           // 5288 edges per graph per edge set
#define NNZ     (NTOT * 8)            // 676864 per edge set

// ---------------- device scratch (static allocation, allowed) ----------------
__device__ int   g_start[4 * NTOT];
__device__ int   g_cnt  [4 * NTOT];
__device__ int2  g_edge [4 * NNZ];    // {col_local, val_bits}, row-sorted per (set,graph)

__device__ float g_e1[NTOT * FDIM];
__device__ float g_f1[NTOT * FDIM];
__device__ float g_e2[NTOT * FDIM];
__device__ float g_f2[NTOT * FDIM];
__device__ float g_e3[NTOT * FDIM];
__device__ float g_f3[NTOT * FDIM];
__device__ float g_ne[NTOT * FDIM];
__device__ float g_nf[NTOT * FDIM];
__device__ float g_att[8 * NGRAPH];   // [k 0..7][graph]; 0..3 e-side, 4..7 f-side

// ---------------------------------------------------------------------------
// K1: fused CSR build. CTA per (set, graph): smem histogram -> smem scan ->
// smem-cursor scatter into packed edge array. Also zeroes g_att (block 0).
__global__ void __launch_bounds__(1024)
build_csr_kernel(const int* __restrict__ r0, const int* __restrict__ c0, const float* __restrict__ v0,
                 const int* __restrict__ r1, const int* __restrict__ c1, const float* __restrict__ v1,
                 const int* __restrict__ r2, const int* __restrict__ c2, const float* __restrict__ v2,
                 const int* __restrict__ r3, const int* __restrict__ c3, const float* __restrict__ v3) {
    __shared__ int sm[1024];      // histogram then inclusive scan
    __shared__ int scur[NODES];   // scatter cursors

    const int s = blockIdx.x >> 7;
    const int g = blockIdx.x & 127;
    const int t = threadIdx.x;

    if (blockIdx.x == 0 && t < 8 * NGRAPH) g_att[t] = 0.0f;

    const int*   rw = (s == 0) ? r0 : (s == 1) ? r1 : (s == 2) ? r2 : r3;
    const int*   cw = (s == 0) ? c0 : (s == 1) ? c1 : (s == 2) ? c2 : c3;
    const float* vw = (s == 0) ? v0 : (s == 1) ? v1 : (s == 2) ? v2 : v3;

    const int gbase = g * NODES;
    const int ebase = g * EPG;

    sm[t] = 0;
    __syncthreads();

    // pass 1: histogram (smem atomics)
    for (int i = t; i < EPG; i += 1024) {
        atomicAdd(&sm[rw[ebase + i] - gbase], 1);
    }
    __syncthreads();

    int v = sm[t];
    // inclusive Hillis-Steele scan over 1024
    #pragma unroll
    for (int off = 1; off < 1024; off <<= 1) {
        int add = (t >= off) ? sm[t - off] : 0;
        __syncthreads();
        sm[t] += add;
        __syncthreads();
    }
    if (t < NODES) {
        int start = s * NNZ + ebase + sm[t] - v;   // exclusive prefix, flat index
        g_start[s * NTOT + gbase + t] = start;
        g_cnt  [s * NTOT + gbase + t] = v;
        scur[t] = start;
    }
    __syncthreads();

    // pass 2: scatter into row-sorted packed edges
    for (int i = t; i < EPG; i += 1024) {
        int   r  = rw[ebase + i] - gbase;
        int   cl = cw[ebase + i] - gbase;
        float vv = vw[ebase + i];
        int p = atomicAdd(&scur[r], 1);
        g_edge[p] = make_int2(cl, __float_as_int(vv));
    }
}

// ---------------------------------------------------------------------------
__device__ __forceinline__ float warp_sum(float v) {
    #pragma unroll
    for (int o = 16; o > 0; o >>= 1) v += __shfl_xor_sync(0xffffffffu, v, o);
    return v;
}

// K2: smem-staged fused SpMM (4 sets) + elementwise + attention partials.
// CTA per (graph, feature-half): stages e/f half interleaved as float2 (169 KB),
// 32 warps; warp handles rows r, r+32, ... Per edge: 1 LDG.64 + 1 LDS.64 + 2 FFMA.
__global__ void __launch_bounds__(1024, 1)
spmm_staged_kernel(const float* __restrict__ e, const float* __restrict__ f,
                   const float* __restrict__ Pd, const float* __restrict__ Qd,
                   const float* __restrict__ Gd, const float* __restrict__ Bd,
                   const float* __restrict__ w_ae, const float* __restrict__ w_af) {
    extern __shared__ float2 sEF[];   // [NODES*32] = 169216 bytes

    const int g     = blockIdx.x >> 1;
    const int half  = blockIdx.x & 1;
    const int tid   = threadIdx.x;
    const int gbase = g * NODES;

    // stage: sEF[node*32 + c] = (e, f) at feature half*32+c
    for (int idx = tid; idx < NODES * 32; idx += 1024) {
        int node = idx >> 5, c = idx & 31;
        int gi = (gbase + node) * FDIM + half * 32 + c;
        sEF[idx] = make_float2(__ldg(&e[gi]), __ldg(&f[gi]));
    }
    __syncthreads();

    const int warp = tid >> 5;
    const int lane = tid & 31;
    const int feat = half * 32 + lane;

    const float wa = __ldg(&w_ae[feat]);
    const float wf = __ldg(&w_af[feat]);
    float att[8];
    #pragma unroll
    for (int k = 0; k < 8; k++) att[k] = 0.0f;

    for (int r = warp; r < NODES; r += 32) {
        const int grow = gbase + r;

        float aE[4], aF[4];
        #pragma unroll
        for (int s = 0; s < 4; s++) {
            const int st  = g_start[s * NTOT + grow];
            const int len = g_cnt  [s * NTOT + grow];
            float sE = 0.0f, sF = 0.0f;
            int j = 0;
            for (; j + 4 <= len; j += 4) {
                int2 e0 = g_edge[st + j];
                int2 e1 = g_edge[st + j + 1];
                int2 e2 = g_edge[st + j + 2];
                int2 e3 = g_edge[st + j + 3];
                float2 g0 = sEF[e0.x * 32 + lane];
                float2 g1 = sEF[e1.x * 32 + lane];
                float2 g2 = sEF[e2.x * 32 + lane];
                float2 g3 = sEF[e3.x * 32 + lane];
                float v0 = __int_as_float(e0.y), v1 = __int_as_float(e1.y);
                float v2 = __int_as_float(e2.y), v3 = __int_as_float(e3.y);
                sE += v0 * g0.x + v1 * g1.x + v2 * g2.x + v3 * g3.x;
                sF += v0 * g0.y + v1 * g1.y + v2 * g2.y + v3 * g3.y;
            }
            for (; j < len; j++) {
                int2 ee = g_edge[st + j];
                float2 gg = sEF[ee.x * 32 + lane];
                float vv = __int_as_float(ee.y);
                sE += vv * gg.x;
                sF += vv * gg.y;
            }
            aE[s] = sE;
            aF[s] = sF;
        }

        const float eG = aE[0], fG = aF[0], eB = aE[1], fB = aF[1];
        const float e1v = aE[2], f1v = aF[2], e2v = aE[3], f2v = aF[3];

        float2 evfv = sEF[r * 32 + lane];
        const float ev = evfv.x, fv = evfv.y;
        const float P = __ldg(&Pd[grow]), Q = __ldg(&Qd[grow]);
        const float G = __ldg(&Gd[grow]), B = __ldg(&Bd[grow]);

        const float v2   = ev * ev + fv * fv;
        const float invb = 1.0f / (v2 + 0.1f);
        const float alpha = (P * ev + Q * fv) * invb - eG - fB;
        const float beta  = (Q * ev - P * fv) * invb + fG + eB;
        const float invgb = 1.0f / (G * G + B * B);
        const float e3 = (alpha * G + beta * B) * invgb;
        const float f3 = (beta * G - alpha * B) * invgb;

        const float b1 = eG - fB;
        const float b2 = fG + eB;
        const float P_ = P - v2 * G;
        const float Q_ = Q + v2 * B;
        const float ne = (P_ * b1 + Q_ * b2) * invgb;
        const float nf = (P_ * b2 - Q_ * b1) * invgb;

        const int oi = grow * FDIM + feat;
        g_e3[oi] = e3;  g_f3[oi] = f3;
        g_ne[oi] = ne;  g_nf[oi] = nf;
        g_e1[oi] = e1v; g_f1[oi] = f1v;
        g_e2[oi] = e2v; g_f2[oi] = f2v;

        att[0] += wa * e3;  att[1] += wa * ne;  att[2] += wa * e1v; att[3] += wa * e2v;
        att[4] += wf * f3;  att[5] += wf * nf;  att[6] += wf * f1v; att[7] += wf * f2v;
    }

    // one reduction per warp at the end
    float c0 = warp_sum(att[0]);
    float c1 = warp_sum(att[1]);
    float c2 = warp_sum(att[2]);
    float c3 = warp_sum(att[3]);
    float c4 = warp_sum(att[4]);
    float c5 = warp_sum(att[5]);
    float c6 = warp_sum(att[6]);
    float c7 = warp_sum(att[7]);

    float sel = 0.0f;
    if      (lane == 0) sel = c0;
    else if (lane == 1) sel = c1;
    else if (lane == 2) sel = c2;
    else if (lane == 3) sel = c3;
    else if (lane == 4) sel = c4;
    else if (lane == 5) sel = c5;
    else if (lane == 6) sel = c6;
    else if (lane == 7) sel = c7;
    if (lane < 8) atomicAdd(&g_att[lane * NGRAPH + g], sel);
}

// ---------------------------------------------------------------------------
// K3: register-blocked concat-GEMM + tanh (8x8 thread tile, fma.rn.f32x2).
__device__ __forceinline__ unsigned long long fma2(unsigned long long a,
                                                   unsigned long long b,
                                                   unsigned long long c) {
    unsigned long long d;
    asm("fma.rn.f32x2 %0, %1, %2, %3;" : "=l"(d) : "l"(a), "l"(b), "l"(c));
    return d;
}
__device__ __forceinline__ unsigned long long pack2(float x) {
    unsigned long long d;
    asm("mov.b64 %0, {%1, %1};" : "=l"(d) : "f"(x));
    return d;
}
__device__ __forceinline__ float tanh_approx(float x) {
    float y;
    asm("tanh.approx.f32 %0, %1;" : "=f"(y) : "f"(x));
    return y;
}

#define XS_PITCH 65
#define W_PITCH  68

__global__ void __launch_bounds__(256, 2)
gemm_kernel(const float* __restrict__ e, const float* __restrict__ f,
            const float* __restrict__ W1, const float* __restrict__ bv1,
            const float* __restrict__ W2, const float* __restrict__ bv2,
            const float* __restrict__ b_ae, const float* __restrict__ b_af,
            float* __restrict__ out) {
    extern __shared__ float sm[];
    float* xs   = sm;                         // [256][65]
    float* Wsm  = sm + 256 * XS_PITCH;        // [64][68]
    float* as_s = Wsm + 64 * W_PITCH;         // [4][256]

    const int side    = blockIdx.y;
    const int tid     = threadIdx.x;
    const int rowbase = blockIdx.x * 256;
    const int nrows   = min(256, NTOT - rowbase);

    const float* W  = side ? W2 : W1;
    const float* bv = side ? bv2 : bv1;

    // attention coefficients per row
    if (tid < nrows) {
        int gph = (rowbase + tid) / NODES;
        float bias = side ? b_af[0] : b_ae[0];
        float ssum = 1e-4f;
        float av[4];
        #pragma unroll
        for (int k = 0; k < 4; k++) {
            float sc = g_att[(side * 4 + k) * NGRAPH + gph] * (1.0f / (float)NODES) + bias;
            float sg = 1.0f / (1.0f + expf(-sc));
            av[k] = sg;
            ssum += sg;
        }
        float inv = 1.0f / ssum;
        #pragma unroll
        for (int k = 0; k < 4; k++) as_s[k * 256 + tid] = av[k] * inv;
    } else {
        #pragma unroll
        for (int k = 0; k < 4; k++) as_s[k * 256 + tid] = 0.0f;
    }

    const int cg = tid & 7;    // col group
    const int rg = tid >> 3;   // row group

    unsigned long long acc[8][4];
    {
        #pragma unroll
        for (int j2 = 0; j2 < 4; j2++) {
            float b0 = bv[cg * 8 + 2 * j2];
            float b1 = bv[cg * 8 + 2 * j2 + 1];
            unsigned long long bb;
            asm("mov.b64 %0, {%1, %2};" : "=l"(bb) : "f"(b0), "f"(b1));
            #pragma unroll
            for (int i = 0; i < 8; i++) acc[i][j2] = bb;
        }
    }

    const float* srcs[5];
    if (side == 0) { srcs[0] = g_e3; srcs[1] = g_ne; srcs[2] = g_e1; srcs[3] = g_e2; srcs[4] = e; }
    else           { srcs[0] = g_f3; srcs[1] = g_nf; srcs[2] = g_f1; srcs[3] = g_f2; srcs[4] = f; }

    for (int s = 0; s < 5; s++) {
        __syncthreads();
        const float* src = srcs[s] + (size_t)rowbase * FDIM;
        for (int i = tid; i < nrows * FDIM; i += 256) {
            int rr = i >> 6, kk = i & 63;
            float a = (s < 4) ? as_s[s * 256 + rr] : 1.0f;
            xs[rr * XS_PITCH + kk] = src[i] * a;
        }
        for (int i = tid; i < 4096; i += 256) {
            int j = i >> 6, k = i & 63;
            Wsm[k * W_PITCH + j] = W[j * 320 + s * 64 + k];
        }
        __syncthreads();

        for (int k = 0; k < 64; k++) {
            ulonglong2 wA = *reinterpret_cast<const ulonglong2*>(&Wsm[k * W_PITCH + cg * 8]);
            ulonglong2 wB = *reinterpret_cast<const ulonglong2*>(&Wsm[k * W_PITCH + cg * 8 + 4]);
            unsigned long long w2[4] = { wA.x, wA.y, wB.x, wB.y };
            unsigned long long xp[8];
            #pragma unroll
            for (int i = 0; i < 8; i++) xp[i] = pack2(xs[(rg * 8 + i) * XS_PITCH + k]);
            #pragma unroll
            for (int i = 0; i < 8; i++) {
                #pragma unroll
                for (int j2 = 0; j2 < 4; j2++)
                    acc[i][j2] = fma2(xp[i], w2[j2], acc[i][j2]);
            }
        }
    }

    #pragma unroll
    for (int i = 0; i < 8; i++) {
        int lr = rg * 8 + i;
        if (lr < nrows) {
            int row = rowbase + lr;
            float* op = out + (size_t)side * NTOT * FDIM + (size_t)row * FDIM + cg * 8;
            union { unsigned long long u; float2 f2; } u0, u1, u2, u3;
            u0.u = acc[i][0]; u1.u = acc[i][1]; u2.u = acc[i][2]; u3.u = acc[i][3];
            float4 o0, o1;
            o0.x = tanh_approx(u0.f2.x); o0.y = tanh_approx(u0.f2.y);
            o0.z = tanh_approx(u1.f2.x); o0.w = tanh_approx(u1.f2.y);
            o1.x = tanh_approx(u2.f2.x); o1.y = tanh_approx(u2.f2.y);
            o1.z = tanh_approx(u3.f2.x); o1.w = tanh_approx(u3.f2.y);
            ((float4*)op)[0] = o0;
            ((float4*)op)[1] = o1;
        }
    }
}

// ---------------------------------------------------------------------------
extern "C" void kernel_launch(void* const* d_in, const int* in_sizes, int n_in,
                              void* d_out, int out_size) {
    const float* e     = (const float*)d_in[0];
    const float* f     = (const float*)d_in[1];
    const int*   rowsG = (const int*)d_in[2];
    const int*   colsG = (const int*)d_in[3];
    const float* valsG = (const float*)d_in[4];
    const int*   rowsB = (const int*)d_in[5];
    const int*   colsB = (const int*)d_in[6];
    const float* valsB = (const float*)d_in[7];
    const int*   rows1 = (const int*)d_in[8];
    const int*   cols1 = (const int*)d_in[9];
    const float* vals1 = (const float*)d_in[10];
    const int*   rows2 = (const int*)d_in[11];
    const int*   cols2 = (const int*)d_in[12];
    const float* vals2 = (const float*)d_in[13];
    const float* G_diag = (const float*)d_in[14];
    const float* B_diag = (const float*)d_in[15];
    const float* Pd    = (const float*)d_in[16];
    const float* Qd    = (const float*)d_in[17];
    const float* W_v1  = (const float*)d_in[18];
    const float* b_v1  = (const float*)d_in[19];
    const float* W_v2  = (const float*)d_in[20];
    const float* b_v2  = (const float*)d_in[21];
    const float* w_ae  = (const float*)d_in[22];
    const float* b_ae  = (const float*)d_in[23];
    const float* w_af  = (const float*)d_in[24];
    const float* b_af  = (const float*)d_in[25];
    float* out = (float*)d_out;

    const int spmm_smem = NODES * 32 * (int)sizeof(float2);                   // 169216
    const int gemm_smem = (256 * XS_PITCH + 64 * W_PITCH + 4 * 256) * (int)sizeof(float);

    static int configured = -1;
    if (configured < 0) {
        cudaFuncSetAttribute(spmm_staged_kernel, cudaFuncAttributeMaxDynamicSharedMemorySize, spmm_smem);
        cudaFuncSetAttribute(gemm_kernel, cudaFuncAttributeMaxDynamicSharedMemorySize, gemm_smem);
        configured = 1;
    }

    build_csr_kernel<<<512, 1024>>>(rowsG, colsG, valsG,
                                    rowsB, colsB, valsB,
                                    rows1, cols1, vals1,
                                    rows2, cols2, vals2);

    spmm_staged_kernel<<<NGRAPH * 2, 1024, spmm_smem>>>(e, f, Pd, Qd, G_diag, B_diag, w_ae, w_af);

    dim3 ggrid((NTOT + 255) / 256, 2);
    gemm_kernel<<<ggrid, 256, gemm_smem>>>(e, f, W_v1, b_v1, W_v2, b_v2, b_ae, b_af, out);
}

// round 4
// speedup vs baseline: 2.2708x; 1.0222x over previous
#include <cuda_runtime.h>
#include <math.h>

#define NODES   661
#define NGRAPH  128
#define NTOT    (NODES * NGRAPH)      // 84608
#define FDIM    64
#define EPG     (NODES * 8)           // 5288 edges per graph per edge set
#define NNZ     (NTOT * 8)            // 676864 per edge set

// ---------------- device scratch (static allocation, allowed) ----------------
__device__ int   g_start[4 * NTOT];
__device__ int   g_cnt  [4 * NTOT];
__device__ int2  g_edge [4 * NNZ];    // {col_local, val_bits}, row-sorted per (set,graph)

__device__ float g_e1[NTOT * FDIM];
__device__ float g_f1[NTOT * FDIM];
__device__ float g_e2[NTOT * FDIM];
__device__ float g_f2[NTOT * FDIM];
__device__ float g_e3[NTOT * FDIM];
__device__ float g_f3[NTOT * FDIM];
__device__ float g_ne[NTOT * FDIM];
__device__ float g_nf[NTOT * FDIM];
__device__ float g_att[8 * NGRAPH];   // [k 0..7][graph]; 0..3 e-side, 4..7 f-side

// ---------------------------------------------------------------------------
// K1: fused CSR build. CTA per (set, graph): smem histogram -> smem scan ->
// smem-cursor scatter into packed edge array. Also zeroes g_att (block 0).
__global__ void __launch_bounds__(1024)
build_csr_kernel(const int* __restrict__ r0, const int* __restrict__ c0, const float* __restrict__ v0,
                 const int* __restrict__ r1, const int* __restrict__ c1, const float* __restrict__ v1,
                 const int* __restrict__ r2, const int* __restrict__ c2, const float* __restrict__ v2,
                 const int* __restrict__ r3, const int* __restrict__ c3, const float* __restrict__ v3) {
    __shared__ int sm[1024];      // histogram then inclusive scan
    __shared__ int scur[NODES];   // scatter cursors

    const int s = blockIdx.x >> 7;
    const int g = blockIdx.x & 127;
    const int t = threadIdx.x;

    if (blockIdx.x == 0 && t < 8 * NGRAPH) g_att[t] = 0.0f;

    const int*   rw = (s == 0) ? r0 : (s == 1) ? r1 : (s == 2) ? r2 : r3;
    const int*   cw = (s == 0) ? c0 : (s == 1) ? c1 : (s == 2) ? c2 : c3;
    const float* vw = (s == 0) ? v0 : (s == 1) ? v1 : (s == 2) ? v2 : v3;

    const int gbase = g * NODES;
    const int ebase = g * EPG;

    sm[t] = 0;
    __syncthreads();

    // pass 1: histogram (smem atomics)
    for (int i = t; i < EPG; i += 1024) {
        atomicAdd(&sm[rw[ebase + i] - gbase], 1);
    }
    __syncthreads();

    int v = sm[t];
    // inclusive Hillis-Steele scan over 1024
    #pragma unroll
    for (int off = 1; off < 1024; off <<= 1) {
        int add = (t >= off) ? sm[t - off] : 0;
        __syncthreads();
        sm[t] += add;
        __syncthreads();
    }
    if (t < NODES) {
        int start = s * NNZ + ebase + sm[t] - v;   // exclusive prefix, flat index
        g_start[s * NTOT + gbase + t] = start;
        g_cnt  [s * NTOT + gbase + t] = v;
        scur[t] = start;
    }
    __syncthreads();

    // pass 2: scatter into row-sorted packed edges
    for (int i = t; i < EPG; i += 1024) {
        int   r  = rw[ebase + i] - gbase;
        int   cl = cw[ebase + i] - gbase;
        float vv = vw[ebase + i];
        int p = atomicAdd(&scur[r], 1);
        g_edge[p] = make_int2(cl, __float_as_int(vv));
    }
}

// ---------------------------------------------------------------------------
__device__ __forceinline__ float warp_sum(float v) {
    #pragma unroll
    for (int o = 16; o > 0; o >>= 1) v += __shfl_xor_sync(0xffffffffu, v, o);
    return v;
}

// K2: smem-staged fused SpMM (4 sets) + elementwise + attention partials.
// CTA per (graph, feature-half): stages e/f half interleaved as float2 (169 KB),
// 32 warps; warp handles rows r, r+32, ... Per edge: 1 LDG.64 + 1 LDS.64 + 2 FFMA.
__global__ void __launch_bounds__(1024, 1)
spmm_staged_kernel(const float* __restrict__ e, const float* __restrict__ f,
                   const float* __restrict__ Pd, const float* __restrict__ Qd,
                   const float* __restrict__ Gd, const float* __restrict__ Bd,
                   const float* __restrict__ w_ae, const float* __restrict__ w_af) {
    extern __shared__ float2 sEF[];   // [NODES*32] = 169216 bytes

    const int g     = blockIdx.x >> 1;
    const int half  = blockIdx.x & 1;
    const int tid   = threadIdx.x;
    const int gbase = g * NODES;

    // stage: sEF[node*32 + c] = (e, f) at feature half*32+c
    for (int idx = tid; idx < NODES * 32; idx += 1024) {
        int node = idx >> 5, c = idx & 31;
        int gi = (gbase + node) * FDIM + half * 32 + c;
        sEF[idx] = make_float2(__ldg(&e[gi]), __ldg(&f[gi]));
    }
    __syncthreads();

    const int warp = tid >> 5;
    const int lane = tid & 31;
    const int feat = half * 32 + lane;

    const float wa = __ldg(&w_ae[feat]);
    const float wf = __ldg(&w_af[feat]);
    float att[8];
    #pragma unroll
    for (int k = 0; k < 8; k++) att[k] = 0.0f;

    for (int r = warp; r < NODES; r += 32) {
        const int grow = gbase + r;

        float aE[4], aF[4];
        #pragma unroll
        for (int s = 0; s < 4; s++) {
            const int st  = g_start[s * NTOT + grow];
            const int len = g_cnt  [s * NTOT + grow];
            float sE = 0.0f, sF = 0.0f;
            int j = 0;
            for (; j + 4 <= len; j += 4) {
                int2 e0 = g_edge[st + j];
                int2 e1 = g_edge[st + j + 1];
                int2 e2 = g_edge[st + j + 2];
                int2 e3 = g_edge[st + j + 3];
                float2 g0 = sEF[e0.x * 32 + lane];
                float2 g1 = sEF[e1.x * 32 + lane];
                float2 g2 = sEF[e2.x * 32 + lane];
                float2 g3 = sEF[e3.x * 32 + lane];
                float v0 = __int_as_float(e0.y), v1 = __int_as_float(e1.y);
                float v2 = __int_as_float(e2.y), v3 = __int_as_float(e3.y);
                sE += v0 * g0.x + v1 * g1.x + v2 * g2.x + v3 * g3.x;
                sF += v0 * g0.y + v1 * g1.y + v2 * g2.y + v3 * g3.y;
            }
            for (; j < len; j++) {
                int2 ee = g_edge[st + j];
                float2 gg = sEF[ee.x * 32 + lane];
                float vv = __int_as_float(ee.y);
                sE += vv * gg.x;
                sF += vv * gg.y;
            }
            aE[s] = sE;
            aF[s] = sF;
        }

        const float eG = aE[0], fG = aF[0], eB = aE[1], fB = aF[1];
        const float e1v = aE[2], f1v = aF[2], e2v = aE[3], f2v = aF[3];

        float2 evfv = sEF[r * 32 + lane];
        const float ev = evfv.x, fv = evfv.y;
        const float P = __ldg(&Pd[grow]), Q = __ldg(&Qd[grow]);
        const float G = __ldg(&Gd[grow]), B = __ldg(&Bd[grow]);

        const float v2   = ev * ev + fv * fv;
        const float invb = 1.0f / (v2 + 0.1f);
        const float alpha = (P * ev + Q * fv) * invb - eG - fB;
        const float beta  = (Q * ev - P * fv) * invb + fG + eB;
        const float invgb = 1.0f / (G * G + B * B);
        const float e3 = (alpha * G + beta * B) * invgb;
        const float f3 = (beta * G - alpha * B) * invgb;

        const float b1 = eG - fB;
        const float b2 = fG + eB;
        const float P_ = P - v2 * G;
        const float Q_ = Q + v2 * B;
        const float ne = (P_ * b1 + Q_ * b2) * invgb;
        const float nf = (P_ * b2 - Q_ * b1) * invgb;

        const int oi = grow * FDIM + feat;
        g_e3[oi] = e3;  g_f3[oi] = f3;
        g_ne[oi] = ne;  g_nf[oi] = nf;
        g_e1[oi] = e1v; g_f1[oi] = f1v;
        g_e2[oi] = e2v; g_f2[oi] = f2v;

        att[0] += wa * e3;  att[1] += wa * ne;  att[2] += wa * e1v; att[3] += wa * e2v;
        att[4] += wf * f3;  att[5] += wf * nf;  att[6] += wf * f1v; att[7] += wf * f2v;
    }

    // one reduction per warp at the end
    float c0 = warp_sum(att[0]);
    float c1 = warp_sum(att[1]);
    float c2 = warp_sum(att[2]);
    float c3 = warp_sum(att[3]);
    float c4 = warp_sum(att[4]);
    float c5 = warp_sum(att[5]);
    float c6 = warp_sum(att[6]);
    float c7 = warp_sum(att[7]);

    float sel = 0.0f;
    if      (lane == 0) sel = c0;
    else if (lane == 1) sel = c1;
    else if (lane == 2) sel = c2;
    else if (lane == 3) sel = c3;
    else if (lane == 4) sel = c4;
    else if (lane == 5) sel = c5;
    else if (lane == 6) sel = c6;
    else if (lane == 7) sel = c7;
    if (lane < 8) atomicAdd(&g_att[lane * NGRAPH + g], sel);
}

// ---------------------------------------------------------------------------
// K3: register-blocked concat-GEMM + tanh (8x8 thread tile, fma.rn.f32x2).
__device__ __forceinline__ unsigned long long fma2(unsigned long long a,
                                                   unsigned long long b,
                                                   unsigned long long c) {
    unsigned long long d;
    asm("fma.rn.f32x2 %0, %1, %2, %3;" : "=l"(d) : "l"(a), "l"(b), "l"(c));
    return d;
}
__device__ __forceinline__ unsigned long long pack2(float x) {
    unsigned long long d;
    asm("mov.b64 %0, {%1, %1};" : "=l"(d) : "f"(x));
    return d;
}
__device__ __forceinline__ float tanh_approx(float x) {
    float y;
    asm("tanh.approx.f32 %0, %1;" : "=f"(y) : "f"(x));
    return y;
}

#define XS_PITCH 65
#define W_PITCH  68

__global__ void __launch_bounds__(256, 2)
gemm_kernel(const float* __restrict__ e, const float* __restrict__ f,
            const float* __restrict__ W1, const float* __restrict__ bv1,
            const float* __restrict__ W2, const float* __restrict__ bv2,
            const float* __restrict__ b_ae, const float* __restrict__ b_af,
            float* __restrict__ out) {
    extern __shared__ float sm[];
    float* xs   = sm;                         // [256][65]
    float* Wsm  = sm + 256 * XS_PITCH;        // [64][68]
    float* as_s = Wsm + 64 * W_PITCH;         // [4][256]

    const int side    = blockIdx.y;
    const int tid     = threadIdx.x;
    const int rowbase = blockIdx.x * 256;
    const int nrows   = min(256, NTOT - rowbase);

    const float* W  = side ? W2 : W1;
    const float* bv = side ? bv2 : bv1;

    // attention coefficients per row
    if (tid < nrows) {
        int gph = (rowbase + tid) / NODES;
        float bias = side ? b_af[0] : b_ae[0];
        float ssum = 1e-4f;
        float av[4];
        #pragma unroll
        for (int k = 0; k < 4; k++) {
            float sc = g_att[(side * 4 + k) * NGRAPH + gph] * (1.0f / (float)NODES) + bias;
            float sg = 1.0f / (1.0f + expf(-sc));
            av[k] = sg;
            ssum += sg;
        }
        float inv = 1.0f / ssum;
        #pragma unroll
        for (int k = 0; k < 4; k++) as_s[k * 256 + tid] = av[k] * inv;
    } else {
        #pragma unroll
        for (int k = 0; k < 4; k++) as_s[k * 256 + tid] = 0.0f;
    }

    const int cg = tid & 7;    // col group
    const int rg = tid >> 3;   // row group

    unsigned long long acc[8][4];
    {
        #pragma unroll
        for (int j2 = 0; j2 < 4; j2++) {
            float b0 = bv[cg * 8 + 2 * j2];
            float b1 = bv[cg * 8 + 2 * j2 + 1];
            unsigned long long bb;
            asm("mov.b64 %0, {%1, %2};" : "=l"(bb) : "f"(b0), "f"(b1));
            #pragma unroll
            for (int i = 0; i < 8; i++) acc[i][j2] = bb;
        }
    }

    const float* srcs[5];
    if (side == 0) { srcs[0] = g_e3; srcs[1] = g_ne; srcs[2] = g_e1; srcs[3] = g_e2; srcs[4] = e; }
    else           { srcs[0] = g_f3; srcs[1] = g_nf; srcs[2] = g_f1; srcs[3] = g_f2; srcs[4] = f; }

    for (int s = 0; s < 5; s++) {
        __syncthreads();
        const float* src = srcs[s] + (size_t)rowbase * FDIM;
        for (int i = tid; i < nrows * FDIM; i += 256) {
            int rr = i >> 6, kk = i & 63;
            float a = (s < 4) ? as_s[s * 256 + rr] : 1.0f;
            xs[rr * XS_PITCH + kk] = src[i] * a;
        }
        for (int i = tid; i < 4096; i += 256) {
            int j = i >> 6, k = i & 63;
            Wsm[k * W_PITCH + j] = W[j * 320 + s * 64 + k];
        }
        __syncthreads();

        for (int k = 0; k < 64; k++) {
            ulonglong2 wA = *reinterpret_cast<const ulonglong2*>(&Wsm[k * W_PITCH + cg * 8]);
            ulonglong2 wB = *reinterpret_cast<const ulonglong2*>(&Wsm[k * W_PITCH + cg * 8 + 4]);
            unsigned long long w2[4] = { wA.x, wA.y, wB.x, wB.y };
            unsigned long long xp[8];
            #pragma unroll
            for (int i = 0; i < 8; i++) xp[i] = pack2(xs[(rg * 8 + i) * XS_PITCH + k]);
            #pragma unroll
            for (int i = 0; i < 8; i++) {
                #pragma unroll
                for (int j2 = 0; j2 < 4; j2++)
                    acc[i][j2] = fma2(xp[i], w2[j2], acc[i][j2]);
            }
        }
    }

    #pragma unroll
    for (int i = 0; i < 8; i++) {
        int lr = rg * 8 + i;
        if (lr < nrows) {
            int row = rowbase + lr;
            float* op = out + (size_t)side * NTOT * FDIM + (size_t)row * FDIM + cg * 8;
            union { unsigned long long u; float2 f2; } u0, u1, u2, u3;
            u0.u = acc[i][0]; u1.u = acc[i][1]; u2.u = acc[i][2]; u3.u = acc[i][3];
            float4 o0, o1;
            o0.x = tanh_approx(u0.f2.x); o0.y = tanh_approx(u0.f2.y);
            o0.z = tanh_approx(u1.f2.x); o0.w = tanh_approx(u1.f2.y);
            o1.x = tanh_approx(u2.f2.x); o1.y = tanh_approx(u2.f2.y);
            o1.z = tanh_approx(u3.f2.x); o1.w = tanh_approx(u3.f2.y);
            ((float4*)op)[0] = o0;
            ((float4*)op)[1] = o1;
        }
    }
}

// ---------------------------------------------------------------------------
extern "C" void kernel_launch(void* const* d_in, const int* in_sizes, int n_in,
                              void* d_out, int out_size) {
    const float* e     = (const float*)d_in[0];
    const float* f     = (const float*)d_in[1];
    const int*   rowsG = (const int*)d_in[2];
    const int*   colsG = (const int*)d_in[3];
    const float* valsG = (const float*)d_in[4];
    const int*   rowsB = (const int*)d_in[5];
    const int*   colsB = (const int*)d_in[6];
    const float* valsB = (const float*)d_in[7];
    const int*   rows1 = (const int*)d_in[8];
    const int*   cols1 = (const int*)d_in[9];
    const float* vals1 = (const float*)d_in[10];
    const int*   rows2 = (const int*)d_in[11];
    const int*   cols2 = (const int*)d_in[12];
    const float* vals2 = (const float*)d_in[13];
    const float* G_diag = (const float*)d_in[14];
    const float* B_diag = (const float*)d_in[15];
    const float* Pd    = (const float*)d_in[16];
    const float* Qd    = (const float*)d_in[17];
    const float* W_v1  = (const float*)d_in[18];
    const float* b_v1  = (const float*)d_in[19];
    const float* W_v2  = (const float*)d_in[20];
    const float* b_v2  = (const float*)d_in[21];
    const float* w_ae  = (const float*)d_in[22];
    const float* b_ae  = (const float*)d_in[23];
    const float* w_af  = (const float*)d_in[24];
    const float* b_af  = (const float*)d_in[25];
    float* out = (float*)d_out;

    const int spmm_smem = NODES * 32 * (int)sizeof(float2);                   // 169216
    const int gemm_smem = (256 * XS_PITCH + 64 * W_PITCH + 4 * 256) * (int)sizeof(float);

    static int configured = -1;
    if (configured < 0) {
        cudaFuncSetAttribute(spmm_staged_kernel, cudaFuncAttributeMaxDynamicSharedMemorySize, spmm_smem);
        cudaFuncSetAttribute(gemm_kernel, cudaFuncAttributeMaxDynamicSharedMemorySize, gemm_smem);
        configured = 1;
    }

    build_csr_kernel<<<512, 1024>>>(rowsG, colsG, valsG,
                                    rowsB, colsB, valsB,
                                    rows1, cols1, vals1,
                                    rows2, cols2, vals2);

    spmm_staged_kernel<<<NGRAPH * 2, 1024, spmm_smem>>>(e, f, Pd, Qd, G_diag, B_diag, w_ae, w_af);

    dim3 ggrid((NTOT + 255) / 256, 2);
    gemm_kernel<<<ggrid, 256, gemm_smem>>>(e, f, W_v1, b_v1, W_v2, b_v2, b_ae, b_af, out);
}

// round 5
// speedup vs baseline: 3.9360x; 1.7333x over previous
#include <cuda_runtime.h>
#include <math.h>

#define NODES   661
#define NGRAPH  128
#define NTOT    (NODES * NGRAPH)      // 84608
#define FDIM    64
#define EPG     (NODES * 8)           // 5288 edges per graph per edge set
#define NNZ     (NTOT * 8)            // 676864 per edge set

// ---------------- device scratch (static allocation, allowed) ----------------
__device__ int   g_st4[NTOT * 4];     // per-row starts, packed over 4 edge sets
__device__ int   g_ct4[NTOT * 4];     // per-row counts, packed over 4 edge sets
__device__ int2  g_edge[4 * NNZ];     // {col_local, val_bits}, row-sorted per (set,graph)

__device__ float g_e1[NTOT * FDIM];
__device__ float g_f1[NTOT * FDIM];
__device__ float g_e2[NTOT * FDIM];
__device__ float g_f2[NTOT * FDIM];
__device__ float g_e3[NTOT * FDIM];
__device__ float g_f3[NTOT * FDIM];
__device__ float g_ne[NTOT * FDIM];
__device__ float g_nf[NTOT * FDIM];
__device__ float g_att[8 * NGRAPH];   // [k 0..7][graph]; 0..3 e-side, 4..7 f-side

// ---------------------------------------------------------------------------
// K1: fused CSR build. CTA per (set, graph): smem histogram -> smem scan ->
// smem-cursor scatter into packed edge array. Also zeroes g_att (block 0).
__global__ void __launch_bounds__(1024)
build_csr_kernel(const int* __restrict__ r0, const int* __restrict__ c0, const float* __restrict__ v0,
                 const int* __restrict__ r1, const int* __restrict__ c1, const float* __restrict__ v1,
                 const int* __restrict__ r2, const int* __restrict__ c2, const float* __restrict__ v2,
                 const int* __restrict__ r3, const int* __restrict__ c3, const float* __restrict__ v3) {
    __shared__ int sm[1024];      // histogram then inclusive scan
    __shared__ int scur[NODES];   // scatter cursors

    const int s = blockIdx.x >> 7;
    const int g = blockIdx.x & 127;
    const int t = threadIdx.x;

    if (blockIdx.x == 0 && t < 8 * NGRAPH) g_att[t] = 0.0f;

    const int*   rw = (s == 0) ? r0 : (s == 1) ? r1 : (s == 2) ? r2 : r3;
    const int*   cw = (s == 0) ? c0 : (s == 1) ? c1 : (s == 2) ? c2 : c3;
    const float* vw = (s == 0) ? v0 : (s == 1) ? v1 : (s == 2) ? v2 : v3;

    const int gbase = g * NODES;
    const int ebase = g * EPG;

    sm[t] = 0;
    __syncthreads();

    // pass 1: histogram (smem atomics)
    for (int i = t; i < EPG; i += 1024) {
        atomicAdd(&sm[rw[ebase + i] - gbase], 1);
    }
    __syncthreads();

    int v = sm[t];
    // inclusive Hillis-Steele scan over 1024
    #pragma unroll
    for (int off = 1; off < 1024; off <<= 1) {
        int add = (t >= off) ? sm[t - off] : 0;
        __syncthreads();
        sm[t] += add;
        __syncthreads();
    }
    if (t < NODES) {
        int start = s * NNZ + ebase + sm[t] - v;   // exclusive prefix, flat index
        g_st4[(gbase + t) * 4 + s] = start;
        g_ct4[(gbase + t) * 4 + s] = v;
        scur[t] = start;
    }
    __syncthreads();

    // pass 2: scatter into row-sorted packed edges
    for (int i = t; i < EPG; i += 1024) {
        int   r  = rw[ebase + i] - gbase;
        int   cl = cw[ebase + i] - gbase;
        float vv = vw[ebase + i];
        int p = atomicAdd(&scur[r], 1);
        g_edge[p] = make_int2(cl, __float_as_int(vv));
    }
}

// ---------------------------------------------------------------------------
__device__ __forceinline__ float warp_sum(float v) {
    #pragma unroll
    for (int o = 16; o > 0; o >>= 1) v += __shfl_xor_sync(0xffffffffu, v, o);
    return v;
}

// K2: smem-staged fused SpMM (4 sets) + elementwise + attention partials.
// CTA per (graph, feature-half): stages (e,f) interleaved float2 (169 KB).
// Packed int4 CSR metadata (one LDG.128 for all 4 sets), next-row prefetch,
// 8-deep predicated edge batches for MLP.
__global__ void __launch_bounds__(1024, 1)
spmm_staged_kernel(const float* __restrict__ e, const float* __restrict__ f,
                   const float* __restrict__ Pd, const float* __restrict__ Qd,
                   const float* __restrict__ Gd, const float* __restrict__ Bd,
                   const float* __restrict__ w_ae, const float* __restrict__ w_af) {
    extern __shared__ float2 sEF[];   // [NODES*32] = 169216 bytes

    const int g     = blockIdx.x >> 1;
    const int half  = blockIdx.x & 1;
    const int tid   = threadIdx.x;
    const int gbase = g * NODES;

    // stage: sEF[node*32 + c] = (e, f) at feature half*32+c   (float4 loads)
    for (int idx = tid; idx < NODES * 8; idx += 1024) {
        int node = idx >> 3, c4 = (idx & 7) * 4;
        const float4 ee = *(const float4*)&e[(gbase + node) * FDIM + half * 32 + c4];
        const float4 ff = *(const float4*)&f[(gbase + node) * FDIM + half * 32 + c4];
        float2* dst = &sEF[node * 32 + c4];
        dst[0] = make_float2(ee.x, ff.x);
        dst[1] = make_float2(ee.y, ff.y);
        dst[2] = make_float2(ee.z, ff.z);
        dst[3] = make_float2(ee.w, ff.w);
    }
    __syncthreads();

    const int warp = tid >> 5;
    const int lane = tid & 31;
    const int feat = half * 32 + lane;

    const float wa = w_ae[feat];
    const float wf = w_af[feat];
    float att[8];
    #pragma unroll
    for (int k = 0; k < 8; k++) att[k] = 0.0f;

    const int4* st4p = (const int4*)g_st4;
    const int4* ct4p = (const int4*)g_ct4;

    int4 st4 = st4p[gbase + warp];
    int4 ct4 = ct4p[gbase + warp];

    for (int r = warp; r < NODES; r += 32) {
        const int grow = gbase + r;

        // prefetch next row's metadata (hidden behind this row's edge phase)
        int4 st4n, ct4n;
        if (r + 32 < NODES) {
            st4n = st4p[grow + 32];
            ct4n = ct4p[grow + 32];
        } else {
            st4n = st4; ct4n = ct4;
        }

        const int sts[4] = { st4.x, st4.y, st4.z, st4.w };
        const int cts[4] = { ct4.x, ct4.y, ct4.z, ct4.w };

        float aE[4], aF[4];
        #pragma unroll
        for (int s = 0; s < 4; s++) {
            const int st  = sts[s];
            const int len = cts[s];
            float sE = 0.0f, sF = 0.0f;
            for (int j0 = 0; j0 < len; j0 += 8) {
                int2 ed[8];
                #pragma unroll
                for (int u = 0; u < 8; u++) {
                    int j = j0 + u;
                    ed[u] = (j < len) ? g_edge[st + j] : make_int2(0, 0);
                }
                #pragma unroll
                for (int u = 0; u < 8; u++) {
                    float2 gg = sEF[ed[u].x * 32 + lane];
                    float vv = __int_as_float(ed[u].y);
                    sE += vv * gg.x;
                    sF += vv * gg.y;
                }
            }
            aE[s] = sE;
            aF[s] = sF;
        }

        st4 = st4n;
        ct4 = ct4n;

        const float eG = aE[0], fG = aF[0], eB = aE[1], fB = aF[1];
        const float e1v = aE[2], f1v = aF[2], e2v = aE[3], f2v = aF[3];

        float2 evfv = sEF[r * 32 + lane];
        const float ev = evfv.x, fv = evfv.y;
        const float P = Pd[grow], Q = Qd[grow];
        const float G = Gd[grow], B = Bd[grow];

        const float v2   = ev * ev + fv * fv;
        const float invb = 1.0f / (v2 + 0.1f);
        const float alpha = (P * ev + Q * fv) * invb - eG - fB;
        const float beta  = (Q * ev - P * fv) * invb + fG + eB;
        const float invgb = 1.0f / (G * G + B * B);
        const float e3 = (alpha * G + beta * B) * invgb;
        const float f3 = (beta * G - alpha * B) * invgb;

        const float b1 = eG - fB;
        const float b2 = fG + eB;
        const float P_ = P - v2 * G;
        const float Q_ = Q + v2 * B;
        const float ne = (P_ * b1 + Q_ * b2) * invgb;
        const float nf = (P_ * b2 - Q_ * b1) * invgb;

        const int oi = grow * FDIM + feat;
        g_e3[oi] = e3;  g_f3[oi] = f3;
        g_ne[oi] = ne;  g_nf[oi] = nf;
        g_e1[oi] = e1v; g_f1[oi] = f1v;
        g_e2[oi] = e2v; g_f2[oi] = f2v;

        att[0] += wa * e3;  att[1] += wa * ne;  att[2] += wa * e1v; att[3] += wa * e2v;
        att[4] += wf * f3;  att[5] += wf * nf;  att[6] += wf * f1v; att[7] += wf * f2v;
    }

    // one reduction per warp at the end
    float c0 = warp_sum(att[0]);
    float c1 = warp_sum(att[1]);
    float c2 = warp_sum(att[2]);
    float c3 = warp_sum(att[3]);
    float c4 = warp_sum(att[4]);
    float c5 = warp_sum(att[5]);
    float c6 = warp_sum(att[6]);
    float c7 = warp_sum(att[7]);

    float sel = 0.0f;
    if      (lane == 0) sel = c0;
    else if (lane == 1) sel = c1;
    else if (lane == 2) sel = c2;
    else if (lane == 3) sel = c3;
    else if (lane == 4) sel = c4;
    else if (lane == 5) sel = c5;
    else if (lane == 6) sel = c6;
    else if (lane == 7) sel = c7;
    if (lane < 8) atomicAdd(&g_att[lane * NGRAPH + g], sel);
}

// ---------------------------------------------------------------------------
// K3: register-blocked concat-GEMM + tanh (8x8 thread tile, fma.rn.f32x2).
// NOTE: no min-blocks clause -> 255-reg budget (occupancy 2 comes from smem).
__device__ __forceinline__ unsigned long long fma2(unsigned long long a,
                                                   unsigned long long b,
                                                   unsigned long long c) {
    unsigned long long d;
    asm("fma.rn.f32x2 %0, %1, %2, %3;" : "=l"(d) : "l"(a), "l"(b), "l"(c));
    return d;
}
__device__ __forceinline__ unsigned long long pack2(float x) {
    unsigned long long d;
    asm("mov.b64 %0, {%1, %1};" : "=l"(d) : "f"(x));
    return d;
}
__device__ __forceinline__ float tanh_approx(float x) {
    float y;
    asm("tanh.approx.f32 %0, %1;" : "=f"(y) : "f"(x));
    return y;
}

#define XS_PITCH 65
#define W_PITCH  68

__global__ void __launch_bounds__(256)
gemm_kernel(const float* __restrict__ e, const float* __restrict__ f,
            const float* __restrict__ W1, const float* __restrict__ bv1,
            const float* __restrict__ W2, const float* __restrict__ bv2,
            const float* __restrict__ b_ae, const float* __restrict__ b_af,
            float* __restrict__ out) {
    extern __shared__ float sm[];
    float* xs   = sm;                         // [256][65]
    float* Wsm  = sm + 256 * XS_PITCH;        // [64][68]
    float* as_s = Wsm + 64 * W_PITCH;         // [4][256]

    const int side    = blockIdx.y;
    const int tid     = threadIdx.x;
    const int rowbase = blockIdx.x * 256;
    const int nrows   = min(256, NTOT - rowbase);

    const float* W  = side ? W2 : W1;
    const float* bv = side ? bv2 : bv1;

    // attention coefficients per row
    if (tid < nrows) {
        int gph = (rowbase + tid) / NODES;
        float bias = side ? b_af[0] : b_ae[0];
        float ssum = 1e-4f;
        float av[4];
        #pragma unroll
        for (int k = 0; k < 4; k++) {
            float sc = g_att[(side * 4 + k) * NGRAPH + gph] * (1.0f / (float)NODES) + bias;
            float sg = 1.0f / (1.0f + expf(-sc));
            av[k] = sg;
            ssum += sg;
        }
        float inv = 1.0f / ssum;
        #pragma unroll
        for (int k = 0; k < 4; k++) as_s[k * 256 + tid] = av[k] * inv;
    } else {
        #pragma unroll
        for (int k = 0; k < 4; k++) as_s[k * 256 + tid] = 0.0f;
    }

    const int cg = tid & 7;    // col group
    const int rg = tid >> 3;   // row group

    unsigned long long acc[8][4];
    {
        #pragma unroll
        for (int j2 = 0; j2 < 4; j2++) {
            float b0 = bv[cg * 8 + 2 * j2];
            float b1 = bv[cg * 8 + 2 * j2 + 1];
            unsigned long long bb;
            asm("mov.b64 %0, {%1, %2};" : "=l"(bb) : "f"(b0), "f"(b1));
            #pragma unroll
            for (int i = 0; i < 8; i++) acc[i][j2] = bb;
        }
    }

    for (int s = 0; s < 5; s++) {
        // pick source pointer via switch (keeps pointer array out of registers)
        const float* src;
        if (side == 0) {
            switch (s) {
                case 0: src = g_e3; break;
                case 1: src = g_ne; break;
                case 2: src = g_e1; break;
                case 3: src = g_e2; break;
                default: src = e;   break;
            }
        } else {
            switch (s) {
                case 0: src = g_f3; break;
                case 1: src = g_nf; break;
                case 2: src = g_f1; break;
                case 3: src = g_f2; break;
                default: src = f;   break;
            }
        }
        src += (size_t)rowbase * FDIM;

        __syncthreads();
        for (int i = tid; i < nrows * FDIM; i += 256) {
            int rr = i >> 6, kk = i & 63;
            float a = (s < 4) ? as_s[s * 256 + rr] : 1.0f;
            xs[rr * XS_PITCH + kk] = src[i] * a;
        }
        for (int i = tid; i < 4096; i += 256) {
            int j = i >> 6, k = i & 63;
            Wsm[k * W_PITCH + j] = W[j * 320 + s * 64 + k];
        }
        __syncthreads();

        #pragma unroll 2
        for (int k = 0; k < 64; k++) {
            ulonglong2 wA = *reinterpret_cast<const ulonglong2*>(&Wsm[k * W_PITCH + cg * 8]);
            ulonglong2 wB = *reinterpret_cast<const ulonglong2*>(&Wsm[k * W_PITCH + cg * 8 + 4]);
            unsigned long long w2[4] = { wA.x, wA.y, wB.x, wB.y };
            unsigned long long xp[8];
            #pragma unroll
            for (int i = 0; i < 8; i++) xp[i] = pack2(xs[(rg * 8 + i) * XS_PITCH + k]);
            #pragma unroll
            for (int i = 0; i < 8; i++) {
                #pragma unroll
                for (int j2 = 0; j2 < 4; j2++)
                    acc[i][j2] = fma2(xp[i], w2[j2], acc[i][j2]);
            }
        }
    }

    #pragma unroll
    for (int i = 0; i < 8; i++) {
        int lr = rg * 8 + i;
        if (lr < nrows) {
            int row = rowbase + lr;
            float* op = out + (size_t)side * NTOT * FDIM + (size_t)row * FDIM + cg * 8;
            union { unsigned long long u; float2 f2; } u0, u1, u2, u3;
            u0.u = acc[i][0]; u1.u = acc[i][1]; u2.u = acc[i][2]; u3.u = acc[i][3];
            float4 o0, o1;
            o0.x = tanh_approx(u0.f2.x); o0.y = tanh_approx(u0.f2.y);
            o0.z = tanh_approx(u1.f2.x); o0.w = tanh_approx(u1.f2.y);
            o1.x = tanh_approx(u2.f2.x); o1.y = tanh_approx(u2.f2.y);
            o1.z = tanh_approx(u3.f2.x); o1.w = tanh_approx(u3.f2.y);
            ((float4*)op)[0] = o0;
            ((float4*)op)[1] = o1;
        }
    }
}

// ---------------------------------------------------------------------------
extern "C" void kernel_launch(void* const* d_in, const int* in_sizes, int n_in,
                              void* d_out, int out_size) {
    const float* e     = (const float*)d_in[0];
    const float* f     = (const float*)d_in[1];
    const int*   rowsG = (const int*)d_in[2];
    const int*   colsG = (const int*)d_in[3];
    const float* valsG = (const float*)d_in[4];
    const int*   rowsB = (const int*)d_in[5];
    const int*   colsB = (const int*)d_in[6];
    const float* valsB = (const float*)d_in[7];
    const int*   rows1 = (const int*)d_in[8];
    const int*   cols1 = (const int*)d_in[9];
    const float* vals1 = (const float*)d_in[10];
    const int*   rows2 = (const int*)d_in[11];
    const int*   cols2 = (const int*)d_in[12];
    const float* vals2 = (const float*)d_in[13];
    const float* G_diag = (const float*)d_in[14];
    const float* B_diag = (const float*)d_in[15];
    const float* Pd    = (const float*)d_in[16];
    const float* Qd    = (const float*)d_in[17];
    const float* W_v1  = (const float*)d_in[18];
    const float* b_v1  = (const float*)d_in[19];
    const float* W_v2  = (const float*)d_in[20];
    const float* b_v2  = (const float*)d_in[21];
    const float* w_ae  = (const float*)d_in[22];
    const float* b_ae  = (const float*)d_in[23];
    const float* w_af  = (const float*)d_in[24];
    const float* b_af  = (const float*)d_in[25];
    float* out = (float*)d_out;

    const int spmm_smem = NODES * 32 * (int)sizeof(float2);                   // 169216
    const int gemm_smem = (256 * XS_PITCH + 64 * W_PITCH + 4 * 256) * (int)sizeof(float);

    cudaFuncSetAttribute(spmm_staged_kernel, cudaFuncAttributeMaxDynamicSharedMemorySize, spmm_smem);
    cudaFuncSetAttribute(gemm_kernel, cudaFuncAttributeMaxDynamicSharedMemorySize, gemm_smem);

    build_csr_kernel<<<512, 1024>>>(rowsG, colsG, valsG,
                                    rowsB, colsB, valsB,
                                    rows1, cols1, vals1,
                                    rows2, cols2, vals2);

    spmm_staged_kernel<<<NGRAPH * 2, 1024, spmm_smem>>>(e, f, Pd, Qd, G_diag, B_diag, w_ae, w_af);

    dim3 ggrid((NTOT + 255) / 256, 2);
    gemm_kernel<<<ggrid, 256, gemm_smem>>>(e, f, W_v1, b_v1, W_v2, b_v2, b_ae, b_af, out);
}